// round 7
// baseline (speedup 1.0000x reference)
#include <cuda_runtime.h>
#include <cuda_bf16.h>
#include <stdint.h>
#include <math.h>

#define L_SEQ 4096
#define BATCH 2
#define HID   1024
#define DHEAD 64
#define CHUNK 64
#define NCHUNK (L_SEQ / CHUNK)
#define GAMMA_F 0.96875f
#define LOG2_GAMMA (-0.045803595f)
#define SDEPTH 16   // gamma^(64*16) ~ 7e-15: below fp32 noise

// Scratch (allocation-free rule: __device__ globals)
__device__ float g_Q[BATCH * L_SEQ * DHEAD];
__device__ float g_K[BATCH * L_SEQ * DHEAD];
__device__ float g_V[BATCH * L_SEQ * DHEAD];
__device__ float g_A[BATCH * NCHUNK * DHEAD * DHEAD];

#define MMA16816(d, a, b)                                                   \
    asm volatile(                                                           \
        "mma.sync.aligned.m16n8k16.row.col.f32.bf16.bf16.f32 "              \
        "{%0,%1,%2,%3}, {%4,%5,%6,%7}, {%8,%9}, {%0,%1,%2,%3};\n"           \
        : "+f"(d[0]), "+f"(d[1]), "+f"(d[2]), "+f"(d[3])                    \
        : "r"(a[0]), "r"(a[1]), "r"(a[2]), "r"(a[3]), "r"(b[0]), "r"(b[1]))

// Shared memory reused across the two stages of the fused kernel.
union SmemProj {
    struct {
        __nv_bfloat16 Ah[64][40];
        __nv_bfloat16 Al[64][40];
        __nv_bfloat16 Bh[192][40];   // [n][k], n = 0..63 Q | 64..127 K | 128..191 V
        __nv_bfloat16 Bl[192][40];
    } s1;
    struct {
        float Ks[64][64];   // rotated K, pre-weighted by gamma^(63-r)
        float Vs[64][64];
    } s2;
};

// ---------------------------------------------------------------------------
// Kernel 1: fused QKV projection (bf16 3-pass split MMA, X read ONCE)
//           + xPos rotary epilogue + per-chunk A_j = (decayed K)^T V.
// One block = 64 rows = exactly one retention chunk.  8 warps.
// ---------------------------------------------------------------------------
__global__ __launch_bounds__(256) void fused_proj_kernel(
    const float* __restrict__ X,
    const float* __restrict__ WQ,
    const float* __restrict__ WK,
    const float* __restrict__ WV) {
    __shared__ SmemProj sm;

    const int t    = threadIdx.x;
    const int warp = t >> 5, lane = t & 31;
    const int grp  = lane >> 2, tig = lane & 3;
    const int wm   = warp >> 1;            // 0..3: 16-row tile
    const int wn   = warp & 1;             // 0..1: 96-col tile
    const int m0   = blockIdx.x * 64;

    float acc[12][4];
#pragma unroll
    for (int nt = 0; nt < 12; nt++)
#pragma unroll
        for (int c = 0; c < 4; c++) acc[nt][c] = 0.0f;

    const int xr = t >> 3;          // 0..31
    const int xc = (t & 7) * 4;     // 0..28

    for (int k0 = 0; k0 < HID; k0 += 32) {
        // --- load + split X tile (64x32 fp32) ---
#pragma unroll
        for (int i = 0; i < 2; i++) {
            const int row = i * 32 + xr;
            float4 v = *(const float4*)(X + (size_t)(m0 + row) * HID + k0 + xc);
            float vv[4] = {v.x, v.y, v.z, v.w};
#pragma unroll
            for (int e = 0; e < 4; e++) {
                __nv_bfloat16 h = __float2bfloat16(vv[e]);
                sm.s1.Ah[row][xc + e] = h;
                sm.s1.Al[row][xc + e] = __float2bfloat16(vv[e] - __bfloat162float(h));
            }
        }
        // --- load + split + transpose all 3 weight tiles (32 x 192) ---
#pragma unroll
        for (int i = 0; i < 24; i++) {
            const int idx = t + i * 256;          // 0..6143
            const int kk = idx / 192;
            const int n  = idx - kk * 192;        // 0..191
            const int tn = n >> 6;
            const float* Wt = (tn == 0) ? WQ : ((tn == 1) ? WK : WV);
            float v = Wt[(size_t)(k0 + kk) * DHEAD + (n & 63)];
            __nv_bfloat16 h = __float2bfloat16(v);
            sm.s1.Bh[n][kk] = h;
            sm.s1.Bl[n][kk] = __float2bfloat16(v - __bfloat162float(h));
        }
        __syncthreads();

#pragma unroll
        for (int ks = 0; ks < 32; ks += 16) {
            const int r = wm * 16 + grp;
            const int c = ks + tig * 2;
            uint32_t ah[4], al[4];
            ah[0] = *(const uint32_t*)&sm.s1.Ah[r][c];
            ah[1] = *(const uint32_t*)&sm.s1.Ah[r + 8][c];
            ah[2] = *(const uint32_t*)&sm.s1.Ah[r][c + 8];
            ah[3] = *(const uint32_t*)&sm.s1.Ah[r + 8][c + 8];
            al[0] = *(const uint32_t*)&sm.s1.Al[r][c];
            al[1] = *(const uint32_t*)&sm.s1.Al[r + 8][c];
            al[2] = *(const uint32_t*)&sm.s1.Al[r][c + 8];
            al[3] = *(const uint32_t*)&sm.s1.Al[r + 8][c + 8];
#pragma unroll
            for (int nt = 0; nt < 12; nt++) {
                const int n = wn * 96 + nt * 8 + grp;
                uint32_t bh[2], bl[2];
                bh[0] = *(const uint32_t*)&sm.s1.Bh[n][c];
                bh[1] = *(const uint32_t*)&sm.s1.Bh[n][c + 8];
                bl[0] = *(const uint32_t*)&sm.s1.Bl[n][c];
                bl[1] = *(const uint32_t*)&sm.s1.Bl[n][c + 8];
                MMA16816(acc[nt], ah, bh);
                MMA16816(acc[nt], ah, bl);
                MMA16816(acc[nt], al, bh);
            }
        }
        __syncthreads();
    }

    // --- epilogue: xPos rotary + gmem writes + stage-2 smem for A ---
    const int b = m0 >> 12;                     // batch (m0 / 4096)
#pragma unroll
    for (int nt = 0; nt < 12; nt++) {
        const int col = wn * 96 + nt * 8 + tig * 2;   // 0..190, even
        const int tn  = col >> 6;                      // 0=Q 1=K 2=V
        const int cc  = col & 63;                      // even col within tensor
        float* __restrict__ Out = (tn == 0) ? g_Q : ((tn == 1) ? g_K : g_V);
        const bool dox  = (tn < 2);
        const bool down = (tn == 1);
        float lsv = 0.f, invf = 0.f;
        if (dox) {
            lsv  = __log2f(((float)cc + 25.6f) / 89.6f);
            invf = exp2f((float)(cc >> 1) * (-13.287712379549449f / 32.0f));
        }
#pragma unroll
        for (int half = 0; half < 2; half++) {
            const int rloc = wm * 16 + grp + half * 8;   // 0..63 in chunk
            const int rr   = m0 + rloc;
            float x0 = acc[nt][half * 2 + 0];
            float x1 = acc[nt][half * 2 + 1];
            if (dox) {
                const float pos = (float)(rr & (L_SEQ - 1));
                float e = lsv * pos * (1.0f / 512.0f);
                if (down) e = -e;
                const float sc = exp2f(e);
                float s, cg;
                sincosf(pos * invf, &s, &cg);
                s *= sc; cg *= sc;
                const float y0 = x0 * cg - x1 * s;
                const float y1 = x1 * cg + x0 * s;
                x0 = y0; x1 = y1;
            }
            *(float2*)(Out + (size_t)rr * DHEAD + cc) = make_float2(x0, x1);
            if (tn == 1) {   // decayed K for A
                const float w = exp2f((float)(CHUNK - 1 - rloc) * LOG2_GAMMA);
                sm.s2.Ks[rloc][cc]     = x0 * w;
                sm.s2.Ks[rloc][cc + 1] = x1 * w;
            } else if (tn == 2) {
                sm.s2.Vs[rloc][cc]     = x0;
                sm.s2.Vs[rloc][cc + 1] = x1;
            }
        }
    }
    __syncthreads();

    // --- stage 2: A_j[d1][d2] = sum_r Ks[r][d1] * Vs[r][d2] ---
    {
        const int ty = t >> 4, tx = t & 15;
        float a4[4][4];
#pragma unroll
        for (int i = 0; i < 4; i++)
#pragma unroll
            for (int jj = 0; jj < 4; jj++) a4[i][jj] = 0.0f;

        for (int r = 0; r < CHUNK; r++) {
            float a[4], v[4];
#pragma unroll
            for (int i = 0; i < 4; i++) a[i] = sm.s2.Ks[r][ty * 4 + i];
#pragma unroll
            for (int jj = 0; jj < 4; jj++) v[jj] = sm.s2.Vs[r][tx * 4 + jj];
#pragma unroll
            for (int i = 0; i < 4; i++)
#pragma unroll
                for (int jj = 0; jj < 4; jj++) a4[i][jj] = fmaf(a[i], v[jj], a4[i][jj]);
        }
        const int j = (m0 & (L_SEQ - 1)) >> 6;
        float* __restrict__ Ap = g_A + (size_t)(b * NCHUNK + j) * DHEAD * DHEAD;
#pragma unroll
        for (int i = 0; i < 4; i++)
#pragma unroll
            for (int jj = 0; jj < 4; jj++)
                Ap[(ty * 4 + i) * DHEAD + tx * 4 + jj] = a4[i][jj];
    }
}

// ---------------------------------------------------------------------------
// Kernel 2: per-chunk output with inlined windowed state.
// O[r] = sum_{r'<=r} g^(r-r') (q_r.k_r') v_r'  +  g^(r+1) q_r . S_j,
// S_j = sum_{d=1..16} gC^(d-1) A_{j-d}.   Split over 2 column halves (z).
// ---------------------------------------------------------------------------
__global__ __launch_bounds__(256) void out_kernel(float* __restrict__ O) {
    const int j  = blockIdx.x;
    const int b  = blockIdx.y;
    const int cb = blockIdx.z * 32;   // column base for phases 2/3

    __shared__ float Qs[CHUNK][DHEAD + 1];
    __shared__ float Ks[CHUNK][DHEAD + 1];
    __shared__ float Ps[CHUNK][DHEAD + 1];
    __shared__ float Ts[CHUNK][33];   // V, then S slice (32 cols)
    __shared__ float gpow[CHUNK + 1];

    const int t = threadIdx.x;
    const size_t base = (size_t)(b * L_SEQ + j * CHUNK) * DHEAD;

    for (int i = t; i < CHUNK * DHEAD; i += 256) {
        const int r = i >> 6, d = i & 63;
        Qs[r][d] = g_Q[base + i];
        Ks[r][d] = g_K[base + i];
    }
    for (int i = t; i < CHUNK * 32; i += 256) {          // prefetch V slice
        const int r = i >> 5, d = i & 31;
        Ts[r][d] = g_V[base + r * DHEAD + cb + d];
    }
    if (t <= CHUNK) gpow[t] = powf(GAMMA_F, (float)t);
    __syncthreads();

    const int ty = t >> 4, tx = t & 15;

    // Phase 1: full P = (Q K^T) * decay-mask
    {
        float p[4][4];
#pragma unroll
        for (int i = 0; i < 4; i++)
#pragma unroll
            for (int jj = 0; jj < 4; jj++) p[i][jj] = 0.0f;
        for (int d = 0; d < DHEAD; d++) {
            float q[4], k[4];
#pragma unroll
            for (int i = 0; i < 4; i++) q[i] = Qs[ty * 4 + i][d];
#pragma unroll
            for (int jj = 0; jj < 4; jj++) k[jj] = Ks[tx * 4 + jj][d];
#pragma unroll
            for (int i = 0; i < 4; i++)
#pragma unroll
                for (int jj = 0; jj < 4; jj++) p[i][jj] = fmaf(q[i], k[jj], p[i][jj]);
        }
#pragma unroll
        for (int i = 0; i < 4; i++) {
            const int r = ty * 4 + i;
#pragma unroll
            for (int jj = 0; jj < 4; jj++) {
                const int rp = tx * 4 + jj;
                Ps[r][rp] = (r >= rp) ? p[i][jj] * gpow[r - rp] : 0.0f;
            }
        }
    }

    // Windowed state slice (gmem -> registers; overlaps with phase-1 tail)
    float s8[8];
#pragma unroll
    for (int e = 0; e < 8; e++) s8[e] = 0.0f;
    {
        const int sr = t >> 2;            // 0..63
        const int sc = (t & 3) * 8;       // 0,8,16,24
        const int dmax = (j < SDEPTH) ? j : SDEPTH;
        const float gC = powf(GAMMA_F, (float)CHUNK);
        float w = 1.0f;
        for (int d = 1; d <= dmax; d++) {
            const float* Ap = g_A + (size_t)(b * NCHUNK + j - d) * 4096;
            float4 u0 = *(const float4*)(Ap + sr * DHEAD + cb + sc);
            float4 u1 = *(const float4*)(Ap + sr * DHEAD + cb + sc + 4);
            s8[0] += w * u0.x; s8[1] += w * u0.y; s8[2] += w * u0.z; s8[3] += w * u0.w;
            s8[4] += w * u1.x; s8[5] += w * u1.y; s8[6] += w * u1.z; s8[7] += w * u1.w;
            w *= gC;
        }
    }
    __syncthreads();   // Ps ready

    // Phase 2: O(cols cb..cb+31) = P @ V
    float o[4][2];
#pragma unroll
    for (int i = 0; i < 4; i++) { o[i][0] = 0.f; o[i][1] = 0.f; }
    for (int r2 = 0; r2 < CHUNK; r2++) {
        float pp[4];
#pragma unroll
        for (int i = 0; i < 4; i++) pp[i] = Ps[ty * 4 + i][r2];
        const float v0 = Ts[r2][tx * 2 + 0];
        const float v1 = Ts[r2][tx * 2 + 1];
#pragma unroll
        for (int i = 0; i < 4; i++) {
            o[i][0] = fmaf(pp[i], v0, o[i][0]);
            o[i][1] = fmaf(pp[i], v1, o[i][1]);
        }
    }
    __syncthreads();   // everyone done reading Ts (V)

    // Store S slice into Ts
    {
        const int sr = t >> 2;
        const int sc = (t & 3) * 8;
#pragma unroll
        for (int e = 0; e < 8; e++) Ts[sr][sc + e] = s8[e];
    }
    __syncthreads();

    // Phase 3: cross-chunk O += gamma^(r+1) * (Q @ S_j)
    float cc[4][2];
#pragma unroll
    for (int i = 0; i < 4; i++) { cc[i][0] = 0.f; cc[i][1] = 0.f; }
    for (int d2 = 0; d2 < DHEAD; d2++) {
        float q[4];
#pragma unroll
        for (int i = 0; i < 4; i++) q[i] = Qs[ty * 4 + i][d2];
        const float s0 = Ts[d2][tx * 2 + 0];
        const float s1 = Ts[d2][tx * 2 + 1];
#pragma unroll
        for (int i = 0; i < 4; i++) {
            cc[i][0] = fmaf(q[i], s0, cc[i][0]);
            cc[i][1] = fmaf(q[i], s1, cc[i][1]);
        }
    }

#pragma unroll
    for (int i = 0; i < 4; i++) {
        const int r = ty * 4 + i;
        const float g = gpow[r + 1];
        const size_t orow = (size_t)(b * L_SEQ + j * CHUNK + r) * DHEAD;
        O[orow + cb + tx * 2 + 0] = o[i][0] + g * cc[i][0];
        O[orow + cb + tx * 2 + 1] = o[i][1] + g * cc[i][1];
    }
}

// ---------------------------------------------------------------------------
extern "C" void kernel_launch(void* const* d_in, const int* in_sizes, int n_in,
                              void* d_out, int out_size) {
    const float* X  = (const float*)d_in[0];
    const float* WQ = (const float*)d_in[1];
    const float* WK = (const float*)d_in[2];
    const float* WV = (const float*)d_in[3];
    float* O = (float*)d_out;

    fused_proj_kernel<<<(BATCH * L_SEQ) / 64, 256>>>(X, WQ, WK, WV);
    out_kernel<<<dim3(NCHUNK, BATCH, 2), 256>>>(O);
}

// round 8
// speedup vs baseline: 1.3934x; 1.3934x over previous
#include <cuda_runtime.h>
#include <cuda_bf16.h>
#include <stdint.h>
#include <math.h>

#define L_SEQ 4096
#define BATCH 2
#define HID   1024
#define DHEAD 64
#define CHUNK 64
#define NCHUNK (L_SEQ / CHUNK)
#define ROWS  (BATCH * L_SEQ)
#define GAMMA_F 0.96875f
#define SDEPTH 16   // gamma^(64*16) ~ 7e-15: below fp32 noise

// Scratch (__device__ globals; no allocations allowed)
__device__ __nv_bfloat16 g_Xh[ROWS * HID];
__device__ __nv_bfloat16 g_Xl[ROWS * HID];
__device__ __nv_bfloat16 g_Wth[3 * DHEAD * HID];   // [which][n][k]
__device__ __nv_bfloat16 g_Wtl[3 * DHEAD * HID];
__device__ float g_Q[ROWS * DHEAD];
__device__ float g_K[ROWS * DHEAD];
__device__ float g_V[ROWS * DHEAD];
__device__ float g_A[BATCH * NCHUNK * DHEAD * DHEAD];

#define MMA16816(d, a, b)                                                   \
    asm volatile(                                                           \
        "mma.sync.aligned.m16n8k16.row.col.f32.bf16.bf16.f32 "              \
        "{%0,%1,%2,%3}, {%4,%5,%6,%7}, {%8,%9}, {%0,%1,%2,%3};\n"           \
        : "+f"(d[0]), "+f"(d[1]), "+f"(d[2]), "+f"(d[3])                    \
        : "r"(a[0]), "r"(a[1]), "r"(a[2]), "r"(a[3]), "r"(b[0]), "r"(b[1]))

// ---------------------------------------------------------------------------
// P0a: split X (fp32) -> packed bf16 hi/lo.  Pure bandwidth.
// Each thread handles 8 consecutive floats.
// ---------------------------------------------------------------------------
__global__ __launch_bounds__(256) void split_x_kernel(const float* __restrict__ X) {
    const size_t tid = (size_t)blockIdx.x * 256 + threadIdx.x;   // 1,048,576 threads
    const float4* p = (const float4*)X + tid * 2;
    float4 a = p[0], b = p[1];
    float v[8] = {a.x, a.y, a.z, a.w, b.x, b.y, b.z, b.w};
    __nv_bfloat162 hh[4], ll[4];
#pragma unroll
    for (int i = 0; i < 4; i++) {
        __nv_bfloat16 h0 = __float2bfloat16(v[2 * i + 0]);
        __nv_bfloat16 h1 = __float2bfloat16(v[2 * i + 1]);
        hh[i] = __nv_bfloat162(h0, h1);
        ll[i] = __nv_bfloat162(__float2bfloat16(v[2 * i + 0] - __bfloat162float(h0)),
                               __float2bfloat16(v[2 * i + 1] - __bfloat162float(h1)));
    }
    *(uint4*)&g_Xh[tid * 8] = *(uint4*)hh;
    *(uint4*)&g_Xl[tid * 8] = *(uint4*)ll;
}

// ---------------------------------------------------------------------------
// P0b: transpose + split W: W[k][n] fp32 -> Wt[which][n][k] bf16 hi/lo.
// ---------------------------------------------------------------------------
__global__ __launch_bounds__(256) void split_w_kernel(
    const float* __restrict__ WQ,
    const float* __restrict__ WK,
    const float* __restrict__ WV) {
    int idx = blockIdx.x * 256 + threadIdx.x;    // 49152 threads, 4 elems each
#pragma unroll
    for (int e = 0; e < 4; e++, idx += 49152) {
        const int which = idx >> 16;
        const int rem   = idx & 65535;
        const int n = rem >> 10, k = rem & 1023;
        const float* W = (which == 0) ? WQ : ((which == 1) ? WK : WV);
        const float v = W[(size_t)k * DHEAD + n];
        __nv_bfloat16 h = __float2bfloat16(v);
        g_Wth[idx] = h;
        g_Wtl[idx] = __float2bfloat16(v - __bfloat162float(h));
    }
}

// ---------------------------------------------------------------------------
// P1: projection. C[64x64] = X[64x1024] @ W[1024x64] per (chunk, which) block.
// Pre-split bf16 operands, BK=64, register-prefetch pipeline, 8 warps.
// 3-pass hi/lo compensated MMA.  xPos epilogue fused.
// ---------------------------------------------------------------------------
__global__ __launch_bounds__(256) void proj_mma_kernel() {
    const int which = blockIdx.y;   // 0=Q, 1=K, 2=V
    float* __restrict__ Out = (which == 0) ? g_Q : ((which == 1) ? g_K : g_V);
    const __nv_bfloat16* __restrict__ Wh = g_Wth + (size_t)which * DHEAD * HID;
    const __nv_bfloat16* __restrict__ Wl = g_Wtl + (size_t)which * DHEAD * HID;

    __shared__ __nv_bfloat16 Ah[64][72];   // pad 8 bf16
    __shared__ __nv_bfloat16 Al[64][72];
    __shared__ __nv_bfloat16 Bh[64][72];
    __shared__ __nv_bfloat16 Bl[64][72];

    const int t    = threadIdx.x;
    const int warp = t >> 5, lane = t & 31;
    const int grp  = lane >> 2, tig = lane & 3;
    const int wm   = warp >> 1;            // 0..3: 16-row tile
    const int wn   = warp & 1;             // 0..1: 32-col tile
    const int m0   = blockIdx.x * 64;

    // load slots: idx in {t, t+256}: row = idx>>3 (0..63), c8 = idx&7 (16B chunk)
    const int r0 = t >> 3, c8 = (t & 7) * 8;
    // (second slot row = r0 + 32)

    uint4 rXh[2], rXl[2], rWh[2], rWl[2];

    auto issue = [&](int k0) {
#pragma unroll
        for (int e = 0; e < 2; e++) {
            const int row = r0 + e * 32;
            const size_t xo = (size_t)(m0 + row) * HID + k0 + c8;
            rXh[e] = *(const uint4*)(g_Xh + xo);
            rXl[e] = *(const uint4*)(g_Xl + xo);
            const size_t wo = (size_t)row * HID + k0 + c8;
            rWh[e] = *(const uint4*)(Wh + wo);
            rWl[e] = *(const uint4*)(Wl + wo);
        }
    };

    float acc[4][4];
#pragma unroll
    for (int nt = 0; nt < 4; nt++)
#pragma unroll
        for (int c = 0; c < 4; c++) acc[nt][c] = 0.0f;

    issue(0);
    for (int k0 = 0; k0 < HID; k0 += 64) {
#pragma unroll
        for (int e = 0; e < 2; e++) {
            const int row = r0 + e * 32;
            *(uint4*)&Ah[row][c8] = rXh[e];
            *(uint4*)&Al[row][c8] = rXl[e];
            *(uint4*)&Bh[row][c8] = rWh[e];
            *(uint4*)&Bl[row][c8] = rWl[e];
        }
        __syncthreads();
        if (k0 + 64 < HID) issue(k0 + 64);

#pragma unroll
        for (int ks = 0; ks < 64; ks += 16) {
            const int r = wm * 16 + grp;
            const int c = ks + tig * 2;
            uint32_t ah[4], al[4];
            ah[0] = *(const uint32_t*)&Ah[r][c];
            ah[1] = *(const uint32_t*)&Ah[r + 8][c];
            ah[2] = *(const uint32_t*)&Ah[r][c + 8];
            ah[3] = *(const uint32_t*)&Ah[r + 8][c + 8];
            al[0] = *(const uint32_t*)&Al[r][c];
            al[1] = *(const uint32_t*)&Al[r + 8][c];
            al[2] = *(const uint32_t*)&Al[r][c + 8];
            al[3] = *(const uint32_t*)&Al[r + 8][c + 8];
#pragma unroll
            for (int nt = 0; nt < 4; nt++) {
                const int n = wn * 32 + nt * 8 + grp;
                uint32_t bh[2], bl[2];
                bh[0] = *(const uint32_t*)&Bh[n][c];
                bh[1] = *(const uint32_t*)&Bh[n][c + 8];
                bl[0] = *(const uint32_t*)&Bl[n][c];
                bl[1] = *(const uint32_t*)&Bl[n][c + 8];
                MMA16816(acc[nt], ah, bh);
                MMA16816(acc[nt], ah, bl);
                MMA16816(acc[nt], al, bh);
            }
        }
        __syncthreads();
    }

    // --- epilogue: xPos rotary for Q (which=0) / K (which=1, downscale) ---
    const bool dox  = (which < 2);
    const bool down = (which == 1);
#pragma unroll
    for (int nt = 0; nt < 4; nt++) {
        const int col = wn * 32 + nt * 8 + tig * 2;   // even column of pair
        const int h   = col >> 1;                      // half index 0..31
        float lsv = 0.f, invf = 0.f;
        if (dox) {
            lsv  = __log2f(((float)col + 25.6f) / 89.6f);
            invf = exp2f((float)h * (-13.287712379549449f / 32.0f));
        }
#pragma unroll
        for (int half = 0; half < 2; half++) {
            const int rr = m0 + wm * 16 + grp + half * 8;
            float x0 = acc[nt][half * 2 + 0];
            float x1 = acc[nt][half * 2 + 1];
            if (dox) {
                const float pos = (float)(rr & (L_SEQ - 1));
                float e = lsv * pos * (1.0f / 512.0f);
                if (down) e = -e;
                const float sc = exp2f(e);
                float s, cg;
                sincosf(pos * invf, &s, &cg);
                s *= sc; cg *= sc;
                const float y0 = x0 * cg - x1 * s;
                const float y1 = x1 * cg + x0 * s;
                x0 = y0; x1 = y1;
            }
            *(float2*)(Out + (size_t)rr * DHEAD + col) = make_float2(x0, x1);
        }
    }
}

// ---------------------------------------------------------------------------
// P2: per-chunk decayed A_j[d1][d2] = sum_r gamma^(63-r) K[r][d1] V[r][d2]
// ---------------------------------------------------------------------------
__global__ __launch_bounds__(256) void chunk_stats_kernel() {
    const int j = blockIdx.x;
    const int b = blockIdx.y;
    __shared__ float Ks[CHUNK][DHEAD];
    __shared__ float Vs[CHUNK][DHEAD];

    const int t = threadIdx.x;
    const size_t base = (size_t)(b * L_SEQ + j * CHUNK) * DHEAD;
    for (int i = t; i < CHUNK * DHEAD; i += 256) {
        const int r = i >> 6, d = i & 63;
        const float w = powf(GAMMA_F, (float)(CHUNK - 1 - r));
        Ks[r][d] = g_K[base + i] * w;
        Vs[r][d] = g_V[base + i];
    }
    __syncthreads();

    const int ty = t >> 4, tx = t & 15;
    float acc[4][4];
#pragma unroll
    for (int i = 0; i < 4; i++)
#pragma unroll
        for (int jj = 0; jj < 4; jj++) acc[i][jj] = 0.0f;

    for (int r = 0; r < CHUNK; r++) {
        float a[4], v[4];
#pragma unroll
        for (int i = 0; i < 4; i++) a[i] = Ks[r][ty * 4 + i];
#pragma unroll
        for (int jj = 0; jj < 4; jj++) v[jj] = Vs[r][tx * 4 + jj];
#pragma unroll
        for (int i = 0; i < 4; i++)
#pragma unroll
            for (int jj = 0; jj < 4; jj++) acc[i][jj] = fmaf(a[i], v[jj], acc[i][jj]);
    }

    float* __restrict__ Ap = g_A + (size_t)(b * NCHUNK + j) * DHEAD * DHEAD;
#pragma unroll
    for (int i = 0; i < 4; i++)
#pragma unroll
        for (int jj = 0; jj < 4; jj++)
            Ap[(ty * 4 + i) * DHEAD + tx * 4 + jj] = acc[i][jj];
}

// ---------------------------------------------------------------------------
// P3: per-chunk output with inlined windowed state (R7 version).
// ---------------------------------------------------------------------------
__global__ __launch_bounds__(256) void out_kernel(float* __restrict__ O) {
    const int j  = blockIdx.x;
    const int b  = blockIdx.y;
    const int cb = blockIdx.z * 32;

    __shared__ float Qs[CHUNK][DHEAD + 1];
    __shared__ float Ks[CHUNK][DHEAD + 1];
    __shared__ float Ps[CHUNK][DHEAD + 1];
    __shared__ float Ts[CHUNK][33];
    __shared__ float gpow[CHUNK + 1];

    const int t = threadIdx.x;
    const size_t base = (size_t)(b * L_SEQ + j * CHUNK) * DHEAD;

    for (int i = t; i < CHUNK * DHEAD; i += 256) {
        const int r = i >> 6, d = i & 63;
        Qs[r][d] = g_Q[base + i];
        Ks[r][d] = g_K[base + i];
    }
    for (int i = t; i < CHUNK * 32; i += 256) {
        const int r = i >> 5, d = i & 31;
        Ts[r][d] = g_V[base + r * DHEAD + cb + d];
    }
    if (t <= CHUNK) gpow[t] = powf(GAMMA_F, (float)t);
    __syncthreads();

    const int ty = t >> 4, tx = t & 15;

    // Phase 1: P = (Q K^T) * decay-mask
    {
        float p[4][4];
#pragma unroll
        for (int i = 0; i < 4; i++)
#pragma unroll
            for (int jj = 0; jj < 4; jj++) p[i][jj] = 0.0f;
        for (int d = 0; d < DHEAD; d++) {
            float q[4], k[4];
#pragma unroll
            for (int i = 0; i < 4; i++) q[i] = Qs[ty * 4 + i][d];
#pragma unroll
            for (int jj = 0; jj < 4; jj++) k[jj] = Ks[tx * 4 + jj][d];
#pragma unroll
            for (int i = 0; i < 4; i++)
#pragma unroll
                for (int jj = 0; jj < 4; jj++) p[i][jj] = fmaf(q[i], k[jj], p[i][jj]);
        }
#pragma unroll
        for (int i = 0; i < 4; i++) {
            const int r = ty * 4 + i;
#pragma unroll
            for (int jj = 0; jj < 4; jj++) {
                const int rp = tx * 4 + jj;
                Ps[r][rp] = (r >= rp) ? p[i][jj] * gpow[r - rp] : 0.0f;
            }
        }
    }

    // Windowed state slice (gmem -> regs)
    float s8[8];
#pragma unroll
    for (int e = 0; e < 8; e++) s8[e] = 0.0f;
    {
        const int sr = t >> 2;
        const int sc = (t & 3) * 8;
        const int dmax = (j < SDEPTH) ? j : SDEPTH;
        const float gC = powf(GAMMA_F, (float)CHUNK);
        float w = 1.0f;
        for (int d = 1; d <= dmax; d++) {
            const float* Ap = g_A + (size_t)(b * NCHUNK + j - d) * 4096;
            float4 u0 = *(const float4*)(Ap + sr * DHEAD + cb + sc);
            float4 u1 = *(const float4*)(Ap + sr * DHEAD + cb + sc + 4);
            s8[0] += w * u0.x; s8[1] += w * u0.y; s8[2] += w * u0.z; s8[3] += w * u0.w;
            s8[4] += w * u1.x; s8[5] += w * u1.y; s8[6] += w * u1.z; s8[7] += w * u1.w;
            w *= gC;
        }
    }
    __syncthreads();

    // Phase 2: O slice = P @ V
    float o[4][2];
#pragma unroll
    for (int i = 0; i < 4; i++) { o[i][0] = 0.f; o[i][1] = 0.f; }
    for (int r2 = 0; r2 < CHUNK; r2++) {
        float pp[4];
#pragma unroll
        for (int i = 0; i < 4; i++) pp[i] = Ps[ty * 4 + i][r2];
        const float v0 = Ts[r2][tx * 2 + 0];
        const float v1 = Ts[r2][tx * 2 + 1];
#pragma unroll
        for (int i = 0; i < 4; i++) {
            o[i][0] = fmaf(pp[i], v0, o[i][0]);
            o[i][1] = fmaf(pp[i], v1, o[i][1]);
        }
    }
    __syncthreads();

    {
        const int sr = t >> 2;
        const int sc = (t & 3) * 8;
#pragma unroll
        for (int e = 0; e < 8; e++) Ts[sr][sc + e] = s8[e];
    }
    __syncthreads();

    // Phase 3: O += gamma^(r+1) * (Q @ S_j)
    float cc[4][2];
#pragma unroll
    for (int i = 0; i < 4; i++) { cc[i][0] = 0.f; cc[i][1] = 0.f; }
    for (int d2 = 0; d2 < DHEAD; d2++) {
        float q[4];
#pragma unroll
        for (int i = 0; i < 4; i++) q[i] = Qs[ty * 4 + i][d2];
        const float s0 = Ts[d2][tx * 2 + 0];
        const float s1 = Ts[d2][tx * 2 + 1];
#pragma unroll
        for (int i = 0; i < 4; i++) {
            cc[i][0] = fmaf(q[i], s0, cc[i][0]);
            cc[i][1] = fmaf(q[i], s1, cc[i][1]);
        }
    }

#pragma unroll
    for (int i = 0; i < 4; i++) {
        const int r = ty * 4 + i;
        const float g = gpow[r + 1];
        const size_t orow = (size_t)(b * L_SEQ + j * CHUNK + r) * DHEAD;
        O[orow + cb + tx * 2 + 0] = o[i][0] + g * cc[i][0];
        O[orow + cb + tx * 2 + 1] = o[i][1] + g * cc[i][1];
    }
}

// ---------------------------------------------------------------------------
extern "C" void kernel_launch(void* const* d_in, const int* in_sizes, int n_in,
                              void* d_out, int out_size) {
    const float* X  = (const float*)d_in[0];
    const float* WQ = (const float*)d_in[1];
    const float* WK = (const float*)d_in[2];
    const float* WV = (const float*)d_in[3];
    float* O = (float*)d_out;

    split_x_kernel<<<4096, 256>>>(X);
    split_w_kernel<<<192, 256>>>(WQ, WK, WV);
    proj_mma_kernel<<<dim3(ROWS / 64, 3), 256>>>();
    chunk_stats_kernel<<<dim3(NCHUNK, BATCH), 256>>>();
    out_kernel<<<dim3(NCHUNK, BATCH, 2), 256>>>(O);
}

// round 9
// speedup vs baseline: 1.4277x; 1.0246x over previous
#include <cuda_runtime.h>
#include <cuda_bf16.h>
#include <stdint.h>
#include <math.h>

#define L_SEQ 4096
#define BATCH 2
#define HID   1024
#define DHEAD 64
#define CHUNK 64
#define NCHUNK (L_SEQ / CHUNK)
#define ROWS  (BATCH * L_SEQ)
#define GAMMA_F 0.96875f
#define LOG2_GAMMA (-0.04580368961f)
#define SDEPTH 16   // gamma^(64*16) ~ 7e-15: below fp32 noise

// Scratch (__device__ globals; no allocations allowed)
__device__ __nv_bfloat16 g_Xh[ROWS * HID];
__device__ __nv_bfloat16 g_Xl[ROWS * HID];
__device__ __nv_bfloat16 g_Wth[3 * DHEAD * HID];   // [which][n][k]
__device__ __nv_bfloat16 g_Wtl[3 * DHEAD * HID];
__device__ float g_Q[ROWS * DHEAD];
__device__ float g_K[ROWS * DHEAD];
__device__ float g_V[ROWS * DHEAD];
__device__ float g_A[BATCH * NCHUNK * DHEAD * DHEAD];

#define MMA16816(d, a, b)                                                   \
    asm volatile(                                                           \
        "mma.sync.aligned.m16n8k16.row.col.f32.bf16.bf16.f32 "              \
        "{%0,%1,%2,%3}, {%4,%5,%6,%7}, {%8,%9}, {%0,%1,%2,%3};\n"           \
        : "+f"(d[0]), "+f"(d[1]), "+f"(d[2]), "+f"(d[3])                    \
        : "r"(a[0]), "r"(a[1]), "r"(a[2]), "r"(a[3]), "r"(b[0]), "r"(b[1]))

// ---------------------------------------------------------------------------
// P0: split X (fp32 -> bf16 hi/lo) and transpose+split W, one launch.
// Blocks [0,4096): X (8 floats/thread). Blocks [4096,4288): W.
// ---------------------------------------------------------------------------
__global__ __launch_bounds__(256) void split_kernel(
    const float* __restrict__ X,
    const float* __restrict__ WQ,
    const float* __restrict__ WK,
    const float* __restrict__ WV) {
    if (blockIdx.x < 4096) {
        const size_t tid = (size_t)blockIdx.x * 256 + threadIdx.x;
        const float4* p = (const float4*)X + tid * 2;
        float4 a = p[0], b = p[1];
        float v[8] = {a.x, a.y, a.z, a.w, b.x, b.y, b.z, b.w};
        __nv_bfloat162 hh[4], ll[4];
#pragma unroll
        for (int i = 0; i < 4; i++) {
            __nv_bfloat16 h0 = __float2bfloat16(v[2 * i + 0]);
            __nv_bfloat16 h1 = __float2bfloat16(v[2 * i + 1]);
            hh[i] = __nv_bfloat162(h0, h1);
            ll[i] = __nv_bfloat162(__float2bfloat16(v[2 * i + 0] - __bfloat162float(h0)),
                                   __float2bfloat16(v[2 * i + 1] - __bfloat162float(h1)));
        }
        *(uint4*)&g_Xh[tid * 8] = *(uint4*)hh;
        *(uint4*)&g_Xl[tid * 8] = *(uint4*)ll;
    } else {
        int idx = (blockIdx.x - 4096) * 256 + threadIdx.x;
#pragma unroll
        for (int e = 0; e < 4; e++, idx += 49152) {
            const int which = idx >> 16;
            const int rem   = idx & 65535;
            const int n = rem >> 10, k = rem & 1023;
            const float* W = (which == 0) ? WQ : ((which == 1) ? WK : WV);
            const float v = W[(size_t)k * DHEAD + n];
            __nv_bfloat16 h = __float2bfloat16(v);
            g_Wth[idx] = h;
            g_Wtl[idx] = __float2bfloat16(v - __bfloat162float(h));
        }
    }
}

// ---------------------------------------------------------------------------
// P1: projection. C[64x64] = X[64x1024] @ W[1024x64] per (chunk, which) block.
// Pre-split bf16 operands, BK=64, register-prefetch pipeline, 8 warps.
// 3-pass hi/lo compensated MMA.  xPos epilogue fused.
// ---------------------------------------------------------------------------
__global__ __launch_bounds__(256) void proj_mma_kernel() {
    const int which = blockIdx.y;   // 0=Q, 1=K, 2=V
    float* __restrict__ Out = (which == 0) ? g_Q : ((which == 1) ? g_K : g_V);
    const __nv_bfloat16* __restrict__ Wh = g_Wth + (size_t)which * DHEAD * HID;
    const __nv_bfloat16* __restrict__ Wl = g_Wtl + (size_t)which * DHEAD * HID;

    __shared__ __nv_bfloat16 Ah[64][72];
    __shared__ __nv_bfloat16 Al[64][72];
    __shared__ __nv_bfloat16 Bh[64][72];
    __shared__ __nv_bfloat16 Bl[64][72];

    const int t    = threadIdx.x;
    const int warp = t >> 5, lane = t & 31;
    const int grp  = lane >> 2, tig = lane & 3;
    const int wm   = warp >> 1;
    const int wn   = warp & 1;
    const int m0   = blockIdx.x * 64;

    const int r0 = t >> 3, c8 = (t & 7) * 8;

    uint4 rXh[2], rXl[2], rWh[2], rWl[2];

    auto issue = [&](int k0) {
#pragma unroll
        for (int e = 0; e < 2; e++) {
            const int row = r0 + e * 32;
            const size_t xo = (size_t)(m0 + row) * HID + k0 + c8;
            rXh[e] = *(const uint4*)(g_Xh + xo);
            rXl[e] = *(const uint4*)(g_Xl + xo);
            const size_t wo = (size_t)row * HID + k0 + c8;
            rWh[e] = *(const uint4*)(Wh + wo);
            rWl[e] = *(const uint4*)(Wl + wo);
        }
    };

    float acc[4][4];
#pragma unroll
    for (int nt = 0; nt < 4; nt++)
#pragma unroll
        for (int c = 0; c < 4; c++) acc[nt][c] = 0.0f;

    issue(0);
    for (int k0 = 0; k0 < HID; k0 += 64) {
#pragma unroll
        for (int e = 0; e < 2; e++) {
            const int row = r0 + e * 32;
            *(uint4*)&Ah[row][c8] = rXh[e];
            *(uint4*)&Al[row][c8] = rXl[e];
            *(uint4*)&Bh[row][c8] = rWh[e];
            *(uint4*)&Bl[row][c8] = rWl[e];
        }
        __syncthreads();
        if (k0 + 64 < HID) issue(k0 + 64);

#pragma unroll
        for (int ks = 0; ks < 64; ks += 16) {
            const int r = wm * 16 + grp;
            const int c = ks + tig * 2;
            uint32_t ah[4], al[4];
            ah[0] = *(const uint32_t*)&Ah[r][c];
            ah[1] = *(const uint32_t*)&Ah[r + 8][c];
            ah[2] = *(const uint32_t*)&Ah[r][c + 8];
            ah[3] = *(const uint32_t*)&Ah[r + 8][c + 8];
            al[0] = *(const uint32_t*)&Al[r][c];
            al[1] = *(const uint32_t*)&Al[r + 8][c];
            al[2] = *(const uint32_t*)&Al[r][c + 8];
            al[3] = *(const uint32_t*)&Al[r + 8][c + 8];
#pragma unroll
            for (int nt = 0; nt < 4; nt++) {
                const int n = wn * 32 + nt * 8 + grp;
                uint32_t bh[2], bl[2];
                bh[0] = *(const uint32_t*)&Bh[n][c];
                bh[1] = *(const uint32_t*)&Bh[n][c + 8];
                bl[0] = *(const uint32_t*)&Bl[n][c];
                bl[1] = *(const uint32_t*)&Bl[n][c + 8];
                MMA16816(acc[nt], ah, bh);
                MMA16816(acc[nt], ah, bl);
                MMA16816(acc[nt], al, bh);
            }
        }
        __syncthreads();
    }

    const bool dox  = (which < 2);
    const bool down = (which == 1);
#pragma unroll
    for (int nt = 0; nt < 4; nt++) {
        const int col = wn * 32 + nt * 8 + tig * 2;
        const int h   = col >> 1;
        float lsv = 0.f, invf = 0.f;
        if (dox) {
            lsv  = __log2f(((float)col + 25.6f) / 89.6f);
            invf = exp2f((float)h * (-13.287712379549449f / 32.0f));
        }
#pragma unroll
        for (int half = 0; half < 2; half++) {
            const int rr = m0 + wm * 16 + grp + half * 8;
            float x0 = acc[nt][half * 2 + 0];
            float x1 = acc[nt][half * 2 + 1];
            if (dox) {
                const float pos = (float)(rr & (L_SEQ - 1));
                float e = lsv * pos * (1.0f / 512.0f);
                if (down) e = -e;
                const float sc = exp2f(e);
                float s, cg;
                sincosf(pos * invf, &s, &cg);
                s *= sc; cg *= sc;
                const float y0 = x0 * cg - x1 * s;
                const float y1 = x1 * cg + x0 * s;
                x0 = y0; x1 = y1;
            }
            *(float2*)(Out + (size_t)rr * DHEAD + col) = make_float2(x0, x1);
        }
    }
}

// ---------------------------------------------------------------------------
// P2: per-chunk decayed A_j[d1][d2] = sum_r gamma^(63-r) K[r][d1] V[r][d2].
// z-split over 2 column halves -> 256 blocks. exp2f decay (no powf).
// ---------------------------------------------------------------------------
__global__ __launch_bounds__(256) void chunk_stats_kernel() {
    const int j  = blockIdx.x;
    const int b  = blockIdx.y;
    const int cb = blockIdx.z * 32;
    __shared__ float Ks[CHUNK][DHEAD];     // decayed K, full 64 cols
    __shared__ float Vs[CHUNK][33];        // V slice, 32 cols

    const int t = threadIdx.x;
    const size_t base = (size_t)(b * L_SEQ + j * CHUNK) * DHEAD;
    for (int i = t; i < CHUNK * DHEAD; i += 256) {
        const int r = i >> 6, d = i & 63;
        const float w = exp2f((float)(CHUNK - 1 - r) * LOG2_GAMMA);
        Ks[r][d] = g_K[base + i] * w;
    }
    for (int i = t; i < CHUNK * 32; i += 256) {
        const int r = i >> 5, d = i & 31;
        Vs[r][d] = g_V[base + r * DHEAD + cb + d];
    }
    __syncthreads();

    const int ty = t >> 4, tx = t & 15;    // 4 rows x 2 cols per thread
    float acc[4][2];
#pragma unroll
    for (int i = 0; i < 4; i++) { acc[i][0] = 0.f; acc[i][1] = 0.f; }

    for (int r = 0; r < CHUNK; r++) {
        float a[4];
#pragma unroll
        for (int i = 0; i < 4; i++) a[i] = Ks[r][ty * 4 + i];
        const float v0 = Vs[r][tx * 2 + 0];
        const float v1 = Vs[r][tx * 2 + 1];
#pragma unroll
        for (int i = 0; i < 4; i++) {
            acc[i][0] = fmaf(a[i], v0, acc[i][0]);
            acc[i][1] = fmaf(a[i], v1, acc[i][1]);
        }
    }

    float* __restrict__ Ap = g_A + (size_t)(b * NCHUNK + j) * DHEAD * DHEAD;
#pragma unroll
    for (int i = 0; i < 4; i++) {
        Ap[(ty * 4 + i) * DHEAD + cb + tx * 2 + 0] = acc[i][0];
        Ap[(ty * 4 + i) * DHEAD + cb + tx * 2 + 1] = acc[i][1];
    }
}

// ---------------------------------------------------------------------------
// P3: per-chunk output with inlined windowed state.  512 threads.
// K stored transposed in smem (conflict-free phase-1 loads).
// ---------------------------------------------------------------------------
__global__ __launch_bounds__(512) void out_kernel(float* __restrict__ O) {
    const int j  = blockIdx.x;
    const int b  = blockIdx.y;
    const int cb = blockIdx.z * 32;

    __shared__ float Qs[CHUNK][DHEAD + 1];
    __shared__ float Kt[DHEAD][CHUNK + 1];   // transposed: [d][r]
    __shared__ float Ps[CHUNK][DHEAD + 1];
    __shared__ float Ts[CHUNK][33];
    __shared__ float gpow[CHUNK + 1];

    const int t = threadIdx.x;
    const size_t base = (size_t)(b * L_SEQ + j * CHUNK) * DHEAD;

    for (int i = t; i < CHUNK * DHEAD; i += 512) {
        const int r = i >> 6, d = i & 63;
        Qs[r][d] = g_Q[base + i];
        Kt[d][r] = g_K[base + i];
    }
    for (int i = t; i < CHUNK * 32; i += 512) {
        const int r = i >> 5, d = i & 31;
        Ts[r][d] = g_V[base + r * DHEAD + cb + d];
    }
    if (t <= CHUNK) gpow[t] = exp2f((float)t * LOG2_GAMMA);
    __syncthreads();

    // Phase 1: P = (Q K^T) * decay-mask.  4 rows x 2 cols per thread.
    {
        const int ty = t >> 5, tx = t & 31;
        float p[4][2];
#pragma unroll
        for (int i = 0; i < 4; i++) { p[i][0] = 0.f; p[i][1] = 0.f; }
        for (int d = 0; d < DHEAD; d++) {
            float q[4];
#pragma unroll
            for (int i = 0; i < 4; i++) q[i] = Qs[ty * 4 + i][d];
            const float k0 = Kt[d][tx * 2 + 0];
            const float k1 = Kt[d][tx * 2 + 1];
#pragma unroll
            for (int i = 0; i < 4; i++) {
                p[i][0] = fmaf(q[i], k0, p[i][0]);
                p[i][1] = fmaf(q[i], k1, p[i][1]);
            }
        }
#pragma unroll
        for (int i = 0; i < 4; i++) {
            const int r = ty * 4 + i;
#pragma unroll
            for (int jj = 0; jj < 2; jj++) {
                const int rp = tx * 2 + jj;
                Ps[r][rp] = (r >= rp) ? p[i][jj] * gpow[r - rp] : 0.0f;
            }
        }
    }

    // Windowed state slice (gmem -> regs): 4 floats per thread
    float s4[4] = {0.f, 0.f, 0.f, 0.f};
    {
        const int sr = t >> 3;            // 0..63
        const int sc = (t & 7) * 4;       // 0..28
        const int dmax = (j < SDEPTH) ? j : SDEPTH;
        const float gC = exp2f((float)CHUNK * LOG2_GAMMA);
        float w = 1.0f;
        for (int d = 1; d <= dmax; d++) {
            const float* Ap = g_A + (size_t)(b * NCHUNK + j - d) * 4096;
            float4 u = *(const float4*)(Ap + sr * DHEAD + cb + sc);
            s4[0] += w * u.x; s4[1] += w * u.y; s4[2] += w * u.z; s4[3] += w * u.w;
            w *= gC;
        }
    }
    __syncthreads();   // Ps ready

    // Phase 2: O slice = P @ V.  2 rows x 2 cols per thread.
    const int ty2 = t >> 4, tx2 = t & 15;
    float o[2][2] = {{0.f, 0.f}, {0.f, 0.f}};
    for (int r2 = 0; r2 < CHUNK; r2++) {
        const float p0 = Ps[ty2 * 2 + 0][r2];
        const float p1 = Ps[ty2 * 2 + 1][r2];
        const float v0 = Ts[r2][tx2 * 2 + 0];
        const float v1 = Ts[r2][tx2 * 2 + 1];
        o[0][0] = fmaf(p0, v0, o[0][0]);
        o[0][1] = fmaf(p0, v1, o[0][1]);
        o[1][0] = fmaf(p1, v0, o[1][0]);
        o[1][1] = fmaf(p1, v1, o[1][1]);
    }
    __syncthreads();   // done reading Ts (V)

    {
        const int sr = t >> 3;
        const int sc = (t & 7) * 4;
#pragma unroll
        for (int e = 0; e < 4; e++) Ts[sr][sc + e] = s4[e];
    }
    __syncthreads();

    // Phase 3: O += gamma^(r+1) * (Q @ S_j)
    float cc[2][2] = {{0.f, 0.f}, {0.f, 0.f}};
    for (int d2 = 0; d2 < DHEAD; d2++) {
        const float q0 = Qs[ty2 * 2 + 0][d2];
        const float q1 = Qs[ty2 * 2 + 1][d2];
        const float s0 = Ts[d2][tx2 * 2 + 0];
        const float s1 = Ts[d2][tx2 * 2 + 1];
        cc[0][0] = fmaf(q0, s0, cc[0][0]);
        cc[0][1] = fmaf(q0, s1, cc[0][1]);
        cc[1][0] = fmaf(q1, s0, cc[1][0]);
        cc[1][1] = fmaf(q1, s1, cc[1][1]);
    }

#pragma unroll
    for (int i = 0; i < 2; i++) {
        const int r = ty2 * 2 + i;
        const float g = gpow[r + 1];
        const size_t orow = (size_t)(b * L_SEQ + j * CHUNK + r) * DHEAD;
        O[orow + cb + tx2 * 2 + 0] = o[i][0] + g * cc[i][0];
        O[orow + cb + tx2 * 2 + 1] = o[i][1] + g * cc[i][1];
    }
}

// ---------------------------------------------------------------------------
extern "C" void kernel_launch(void* const* d_in, const int* in_sizes, int n_in,
                              void* d_out, int out_size) {
    const float* X  = (const float*)d_in[0];
    const float* WQ = (const float*)d_in[1];
    const float* WK = (const float*)d_in[2];
    const float* WV = (const float*)d_in[3];
    float* O = (float*)d_out;

    split_kernel<<<4288, 256>>>(X, WQ, WK, WV);
    proj_mma_kernel<<<dim3(ROWS / 64, 3), 256>>>();
    chunk_stats_kernel<<<dim3(NCHUNK, BATCH, 2), 256>>>();
    out_kernel<<<dim3(NCHUNK, BATCH, 2), 512>>>(O);
}